// round 2
// baseline (speedup 1.0000x reference)
#include <cuda_runtime.h>
#include <cuda_bf16.h>
#include <math.h>
#include <stdint.h>

// Problem constants (fixed by the dataset)
#define NROWS 32768      // 2B * K rows in x (and x_pair)
#define DDIM  256        // feature dim
#define NB    128        // 2B batches
#define MSZ   512        // mask size (K + K')
#define EPSN  1e-8f

// Scratch: normalized rows in bf16 (validates bf16 precision for future tcgen05 path)
__device__ __nv_bfloat16 g_xn [(size_t)NROWS * DDIM];
__device__ __nv_bfloat16 g_xpn[(size_t)NROWS * DDIM];
__device__ float g_pos_partials[4096];
__device__ float g_neg_partials[1024];

// ---------------------------------------------------------------------------
// Kernel 1: per-row L2 normalize (bf16 out) + positive-loss partials
// 1 warp per row, 8 rows per 256-thread block -> 4096 blocks
// ---------------------------------------------------------------------------
__device__ __forceinline__ void store_bf16x4(__nv_bfloat16* dst, int idx4,
                                             float4 v, float scale) {
    __nv_bfloat162 lo = __floats2bfloat162_rn(v.x * scale, v.y * scale);
    __nv_bfloat162 hi = __floats2bfloat162_rn(v.z * scale, v.w * scale);
    uint2 packed;
    packed.x = *reinterpret_cast<uint32_t*>(&lo);
    packed.y = *reinterpret_cast<uint32_t*>(&hi);
    reinterpret_cast<uint2*>(dst)[idx4] = packed;
}

__global__ __launch_bounds__(256) void k_prep(const float* __restrict__ x,
                                              const float* __restrict__ xp) {
    int wid  = threadIdx.x >> 5;
    int lane = threadIdx.x & 31;
    int row  = blockIdx.x * 8 + wid;

    const float4* xr = reinterpret_cast<const float4*>(x)  + (size_t)row * (DDIM / 4);
    const float4* pr = reinterpret_cast<const float4*>(xp) + (size_t)row * (DDIM / 4);

    float4 a0 = xr[lane];
    float4 a1 = xr[lane + 32];
    float4 b0 = pr[lane];
    float4 b1 = pr[lane + 32];

    float sx = a0.x*a0.x + a0.y*a0.y + a0.z*a0.z + a0.w*a0.w
             + a1.x*a1.x + a1.y*a1.y + a1.z*a1.z + a1.w*a1.w;
    float sp = b0.x*b0.x + b0.y*b0.y + b0.z*b0.z + b0.w*b0.w
             + b1.x*b1.x + b1.y*b1.y + b1.z*b1.z + b1.w*b1.w;
    float dp = a0.x*b0.x + a0.y*b0.y + a0.z*b0.z + a0.w*b0.w
             + a1.x*b1.x + a1.y*b1.y + a1.z*b1.z + a1.w*b1.w;

    #pragma unroll
    for (int o = 16; o > 0; o >>= 1) {
        sx += __shfl_xor_sync(0xFFFFFFFFu, sx, o);
        sp += __shfl_xor_sync(0xFFFFFFFFu, sp, o);
        dp += __shfl_xor_sync(0xFFFFFFFFu, dp, o);
    }

    float nx  = fmaxf(sqrtf(sx), EPSN);
    float npp = fmaxf(sqrtf(sp), EPSN);
    float ix  = 1.0f / nx;
    float ip  = 1.0f / npp;

    __nv_bfloat16* on = g_xn  + (size_t)row * DDIM;
    __nv_bfloat16* op = g_xpn + (size_t)row * DDIM;
    store_bf16x4(on, lane,      a0, ix);
    store_bf16x4(on, lane + 32, a1, ix);
    store_bf16x4(op, lane,      b0, ip);
    store_bf16x4(op, lane + 32, b1, ip);

    __shared__ float sm[8];
    if (lane == 0) sm[wid] = dp * ix * ip;   // cosine similarity of this row
    __syncthreads();
    if (threadIdx.x == 0) {
        float t = 0.f;
        #pragma unroll
        for (int i = 0; i < 8; ++i) t += sm[i];
        g_pos_partials[blockIdx.x] = t;
    }
}

// ---------------------------------------------------------------------------
// Kernel 2: per-batch gram matrix + diagonal-masked row logsumexp
// grid = 128 batches * 8 i-tiles (64 rows) = 1024 CTAs, 256 threads
// smem: two [64 rows][128 k-chunk, padded to 132] fp32 tiles = 67,584 B
// thread micro-tile 4x4 over a 64x64 output tile
// ---------------------------------------------------------------------------
#define KPAD 132
#define TILE_FLOATS (64 * KPAD)

__device__ __forceinline__ const __nv_bfloat16* zrow(int gi, int b) {
    // z[b, gi] = gi < 256 ? x[gi*128 + b] : x_pair[(gi-256)*128 + b]
    return (gi < 256)
        ? (g_xn  + ((size_t)(gi * NB + b)) * DDIM)
        : (g_xpn + ((size_t)((gi - 256) * NB + b)) * DDIM);
}

__device__ __forceinline__ void fill_tile(float* s, int t0, int k0, int b, int tid) {
    int lane = tid & 31;
    int w    = tid >> 5;          // 8 warps; warp loads one full 128-dim row chunk
    #pragma unroll
    for (int it = 0; it < 8; ++it) {
        int r = w + it * 8;       // 0..63
        const __nv_bfloat16* src = zrow(t0 + r, b) + k0 + lane * 4;
        uint2 v = *reinterpret_cast<const uint2*>(src);
        __nv_bfloat162 h0 = *reinterpret_cast<__nv_bfloat162*>(&v.x);
        __nv_bfloat162 h1 = *reinterpret_cast<__nv_bfloat162*>(&v.y);
        float2 f0 = __bfloat1622float2(h0);
        float2 f1 = __bfloat1622float2(h1);
        *reinterpret_cast<float4*>(s + r * KPAD + lane * 4) =
            make_float4(f0.x, f0.y, f1.x, f1.y);
    }
}

extern __shared__ float smem_neg[];

__global__ __launch_bounds__(256, 3) void k_neg() {
    int tid = threadIdx.x;
    int b   = blockIdx.x >> 3;          // batch
    int i0  = (blockIdx.x & 7) * 64;    // i-tile base row (0..448)

    int tx  = tid & 15;
    int ty  = tid >> 4;
    int ty4 = ty * 4;
    int tx4 = tx * 4;

    float* si = smem_neg;
    float* sj = smem_neg + TILE_FLOATS;

    float rm[4], rs[4];
    #pragma unroll
    for (int i = 0; i < 4; ++i) { rm[i] = -INFINITY; rs[i] = 0.f; }

    for (int jt = 0; jt < 8; ++jt) {
        int j0 = jt * 64;
        float acc[4][4];
        #pragma unroll
        for (int i = 0; i < 4; ++i)
            #pragma unroll
            for (int j = 0; j < 4; ++j) acc[i][j] = 0.f;

        #pragma unroll
        for (int kc = 0; kc < 2; ++kc) {
            __syncthreads();                 // protect previous smem consumers
            fill_tile(si, i0, kc * 128, b, tid);
            fill_tile(sj, j0, kc * 128, b, tid);
            __syncthreads();

            #pragma unroll 8
            for (int k = 0; k < 128; k += 4) {
                float4 av[4], bv[4];
                #pragma unroll
                for (int i = 0; i < 4; ++i)
                    av[i] = *reinterpret_cast<const float4*>(si + (ty4 + i) * KPAD + k);
                #pragma unroll
                for (int j = 0; j < 4; ++j)
                    bv[j] = *reinterpret_cast<const float4*>(sj + (tx4 + j) * KPAD + k);
                #pragma unroll
                for (int i = 0; i < 4; ++i)
                    #pragma unroll
                    for (int j = 0; j < 4; ++j)
                        acc[i][j] += av[i].x * bv[j].x + av[i].y * bv[j].y
                                   + av[i].z * bv[j].z + av[i].w * bv[j].w;
            }
        }

        // online logsumexp update (sim = dot / TEMP = 2*dot), skip diagonal
        #pragma unroll
        for (int ii = 0; ii < 4; ++ii) {
            int gi = i0 + ty4 + ii;
            #pragma unroll
            for (int jj = 0; jj < 4; ++jj) {
                int gj = j0 + tx4 + jj;
                if (gi == gj) continue;
                float v  = 2.0f * acc[ii][jj];
                float nm = fmaxf(rm[ii], v);
                rs[ii] = rs[ii] * __expf(rm[ii] - nm) + __expf(v - nm);
                rm[ii] = nm;
            }
        }
    }

    // combine (m,s) across the 16 tx threads of each row
    __syncthreads();
    float2* ms = reinterpret_cast<float2*>(smem_neg);   // [64][16]
    #pragma unroll
    for (int ii = 0; ii < 4; ++ii)
        ms[(ty4 + ii) * 16 + tx] = make_float2(rm[ii], rs[ii]);
    __syncthreads();

    float* red = smem_neg + 2048;   // after the 64*16 float2 region
    if (tid < 64) {
        float M = -INFINITY, S = 0.f;
        #pragma unroll
        for (int t = 0; t < 16; ++t) {
            float2 p = ms[tid * 16 + t];
            float nm = fmaxf(M, p.x);
            S = S * __expf(M - nm) + p.y * __expf(p.x - nm);
            M = nm;
        }
        red[tid] = M + logf(S);
    }
    __syncthreads();
    if (tid == 0) {
        float t = 0.f;
        for (int i = 0; i < 64; ++i) t += red[i];
        g_neg_partials[blockIdx.x] = t;   // fixed slot -> deterministic
    }
}

// ---------------------------------------------------------------------------
// Kernel 3: final deterministic reduction -> scalar loss
// ---------------------------------------------------------------------------
__global__ __launch_bounds__(256) void k_final(float* __restrict__ out) {
    __shared__ float rp[256], rn[256];
    int tid = threadIdx.x;
    float sp = 0.f, sn = 0.f;
    for (int i = tid; i < 4096; i += 256) sp += g_pos_partials[i];
    for (int i = tid; i < 1024; i += 256) sn += g_neg_partials[i];
    rp[tid] = sp; rn[tid] = sn;
    __syncthreads();
    for (int o = 128; o > 0; o >>= 1) {
        if (tid < o) { rp[tid] += rp[tid + o]; rn[tid] += rn[tid + o]; }
        __syncthreads();
    }
    if (tid == 0) {
        float loss_neg = rn[0] / (float)(NB * MSZ);          // mean over 128*512 rows
        float loss_pos = rp[0] * 2.0f / (float)NROWS;        // mean(cos)/TEMP, n_pos=1
        out[0] = loss_neg - loss_pos;
    }
}

// ---------------------------------------------------------------------------
extern "C" void kernel_launch(void* const* d_in, const int* in_sizes, int n_in,
                              void* d_out, int out_size) {
    const float* x  = (const float*)d_in[0];
    const float* xp = (const float*)d_in[1];
    float* out = (float*)d_out;

    const int smem_bytes = 2 * TILE_FLOATS * (int)sizeof(float);  // 67,584 B
    cudaFuncSetAttribute(k_neg, cudaFuncAttributeMaxDynamicSharedMemorySize, smem_bytes);

    k_prep<<<NROWS / 8, 256>>>(x, xp);
    k_neg<<<NB * 8, 256, smem_bytes>>>();
    k_final<<<1, 256>>>(out);
}

// round 6
// speedup vs baseline: 12.9803x; 12.9803x over previous
#include <cuda_runtime.h>
#include <cuda_bf16.h>
#include <math.h>
#include <stdint.h>

// Problem constants
#define NROWS 32768      // rows in x (and in x_pair)
#define DDIM  256        // feature dim
#define NB    128        // 2B batches
#define MSZ   512        // mask size
#define EPSN  1e-8f

// Scratch: normalized rows in bf16, per-batch layout [b][gi][d]
__device__ __align__(16) __nv_bfloat16 g_z[(size_t)NB * MSZ * DDIM];
__device__ float g_pos_partials[4096];
__device__ float g_neg_partials[NB * 4];

__device__ __forceinline__ uint32_t smem_u32(const void* p) {
    uint32_t a;
    asm("{ .reg .u64 t; cvta.to.shared.u64 t, %1; cvt.u32.u64 %0, t; }" : "=r"(a) : "l"(p));
    return a;
}

// ---------------------------------------------------------------------------
// Kernel 1: per-row L2 normalize -> bf16 into per-batch layout + pos partials
// ---------------------------------------------------------------------------
__device__ __forceinline__ void store_bf16x4(__nv_bfloat16* dst, int idx4,
                                             float4 v, float scale) {
    __nv_bfloat162 lo = __floats2bfloat162_rn(v.x * scale, v.y * scale);
    __nv_bfloat162 hi = __floats2bfloat162_rn(v.z * scale, v.w * scale);
    uint2 packed;
    packed.x = *reinterpret_cast<uint32_t*>(&lo);
    packed.y = *reinterpret_cast<uint32_t*>(&hi);
    reinterpret_cast<uint2*>(dst)[idx4] = packed;
}

__global__ __launch_bounds__(256) void k_prep(const float* __restrict__ x,
                                              const float* __restrict__ xp) {
    int wid  = threadIdx.x >> 5;
    int lane = threadIdx.x & 31;
    int row  = blockIdx.x * 8 + wid;

    const float4* xr = reinterpret_cast<const float4*>(x)  + (size_t)row * (DDIM / 4);
    const float4* pr = reinterpret_cast<const float4*>(xp) + (size_t)row * (DDIM / 4);

    float4 a0 = xr[lane];
    float4 a1 = xr[lane + 32];
    float4 b0 = pr[lane];
    float4 b1 = pr[lane + 32];

    float sx = a0.x*a0.x + a0.y*a0.y + a0.z*a0.z + a0.w*a0.w
             + a1.x*a1.x + a1.y*a1.y + a1.z*a1.z + a1.w*a1.w;
    float sp = b0.x*b0.x + b0.y*b0.y + b0.z*b0.z + b0.w*b0.w
             + b1.x*b1.x + b1.y*b1.y + b1.z*b1.z + b1.w*b1.w;
    float dp = a0.x*b0.x + a0.y*b0.y + a0.z*b0.z + a0.w*b0.w
             + a1.x*b1.x + a1.y*b1.y + a1.z*b1.z + a1.w*b1.w;

    #pragma unroll
    for (int o = 16; o > 0; o >>= 1) {
        sx += __shfl_xor_sync(0xFFFFFFFFu, sx, o);
        sp += __shfl_xor_sync(0xFFFFFFFFu, sp, o);
        dp += __shfl_xor_sync(0xFFFFFFFFu, dp, o);
    }

    float ix = 1.0f / fmaxf(sqrtf(sx), EPSN);
    float ip = 1.0f / fmaxf(sqrtf(sp), EPSN);

    // z[b, gi] = x[gi*128 + b]; z[b, 256+gi] = x_pair[gi*128 + b]
    int b  = row & 127;
    int gi = row >> 7;
    __nv_bfloat16* on = g_z + ((size_t)b * MSZ + gi) * DDIM;
    __nv_bfloat16* op = g_z + ((size_t)b * MSZ + 256 + gi) * DDIM;
    store_bf16x4(on, lane,      a0, ix);
    store_bf16x4(on, lane + 32, a1, ix);
    store_bf16x4(op, lane,      b0, ip);
    store_bf16x4(op, lane + 32, b1, ip);

    __shared__ float sm[8];
    if (lane == 0) sm[wid] = dp * ix * ip;
    __syncthreads();
    if (threadIdx.x == 0) {
        float t = 0.f;
        #pragma unroll
        for (int i = 0; i < 8; ++i) t += sm[i];
        g_pos_partials[blockIdx.x] = t;
    }
}

// ---------------------------------------------------------------------------
// Kernel 2: per-batch gram via mma.sync bf16 (legacy tensor path, sm_80+ PTX)
// grid = 128 batches x 4 i-tiles = 512 CTAs, 256 threads (8 warps, 4x2 M/N)
// SMEM: A tile [128 x 256 bf16] stride 528B + B double buffer (2 tiles)
// ---------------------------------------------------------------------------
#define AB_STRIDE 528                 // 512B row + 16B pad (conflict-free ldmatrix)
#define TILE_B    (128 * AB_STRIDE)   // 67,584 B
#define SMEM_DYN  (3 * TILE_B)        // 202,752 B

__device__ __forceinline__ void cp_tile(char* dst, const char* src, int tid) {
    uint32_t d = smem_u32(dst);
    #pragma unroll
    for (int i = 0; i < 16; ++i) {
        int idx = tid + i * 256;       // 0..4095: 128 rows x 32 segs of 16B
        int row = idx >> 5;
        int seg = idx & 31;
        asm volatile("cp.async.cg.shared.global [%0], [%1], 16;"
                     :: "r"(d + row * AB_STRIDE + seg * 16),
                        "l"(src + (size_t)row * 512 + seg * 16) : "memory");
    }
}
#define CP_COMMIT() asm volatile("cp.async.commit_group;" ::: "memory")

__device__ __forceinline__ void ldsm_x4(uint32_t* r, uint32_t addr) {
    asm volatile("ldmatrix.sync.aligned.m8n8.x4.shared.b16 {%0,%1,%2,%3}, [%4];"
                 : "=r"(r[0]), "=r"(r[1]), "=r"(r[2]), "=r"(r[3]) : "r"(addr));
}
__device__ __forceinline__ void mma16816(float* c, const uint32_t* a,
                                         uint32_t b0, uint32_t b1) {
    asm volatile("mma.sync.aligned.m16n8k16.row.col.f32.bf16.bf16.f32 "
                 "{%0,%1,%2,%3}, {%4,%5,%6,%7}, {%8,%9}, {%0,%1,%2,%3};"
                 : "+f"(c[0]), "+f"(c[1]), "+f"(c[2]), "+f"(c[3])
                 : "r"(a[0]), "r"(a[1]), "r"(a[2]), "r"(a[3]), "r"(b0), "r"(b1));
}

__global__ __launch_bounds__(256, 1) void k_neg() {
    extern __shared__ char smraw[];
    char* sA  = smraw;
    char* sBb[2] = { smraw + TILE_B, smraw + 2 * TILE_B };
    __shared__ float s_rowsum[128];
    __shared__ float s_red[4];

    const int tid    = threadIdx.x;
    const int w      = tid >> 5;
    const int lane   = tid & 31;
    const int b      = blockIdx.x >> 2;
    const int it     = blockIdx.x & 3;
    const int i0     = it * 128;
    const int warp_m = w & 3;       // 4 M-slices of 32 rows
    const int warp_n = w >> 2;      // 2 N-slices of 64 cols

    const char* zb = reinterpret_cast<const char*>(g_z) + (size_t)b * MSZ * DDIM * 2;

    // prefetch A(i-tile) and B(j=0) as group 0
    cp_tile(sA, zb + (size_t)i0 * 512, tid);
    cp_tile(sBb[0], zb, tid);
    CP_COMMIT();

    if (tid < 128) s_rowsum[tid] = 0.f;

    // per-lane A/B smem base addrs for ldmatrix
    const uint32_t aBase = smem_u32(sA)
        + (uint32_t)(warp_m * 32 + (lane & 15)) * AB_STRIDE + (uint32_t)(lane >> 4) * 16;
    const uint32_t bOff  =                       // within a B tile
          (uint32_t)(warp_n * 64 + (lane >> 4) * 8 + (lane & 7)) * AB_STRIDE
        + (uint32_t)((lane >> 3) & 1) * 16;

    float racc[4] = {0.f, 0.f, 0.f, 0.f};   // row partials: [mi][half]

    for (int j = 0; j < 4; ++j) {
        if (j < 3) {                          // prefetch B(j+1) into other buffer
            cp_tile(sBb[(j + 1) & 1], zb + (size_t)(j + 1) * 128 * 512, tid);
            CP_COMMIT();
            asm volatile("cp.async.wait_group 1;" ::: "memory");
        } else {
            asm volatile("cp.async.wait_group 0;" ::: "memory");
        }
        __syncthreads();                       // B(j) visible everywhere

        const uint32_t bBase = smem_u32(sBb[j & 1]) + bOff;

        float acc[2][8][4];
        #pragma unroll
        for (int mi = 0; mi < 2; ++mi)
            #pragma unroll
            for (int ni = 0; ni < 8; ++ni)
                #pragma unroll
                for (int c = 0; c < 4; ++c) acc[mi][ni][c] = 0.f;

        #pragma unroll 4
        for (int ks = 0; ks < 16; ++ks) {
            uint32_t af[2][4];
            ldsm_x4(af[0], aBase + ks * 32);
            ldsm_x4(af[1], aBase + 16 * AB_STRIDE + ks * 32);
            #pragma unroll
            for (int p = 0; p < 4; ++p) {
                uint32_t bf[4];
                ldsm_x4(bf, bBase + p * 16 * AB_STRIDE + ks * 32);
                #pragma unroll
                for (int mi = 0; mi < 2; ++mi) {
                    mma16816(acc[mi][p * 2 + 0], af[mi], bf[0], bf[1]);
                    mma16816(acc[mi][p * 2 + 1], af[mi], bf[2], bf[3]);
                }
            }
        }

        // epilogue: exp(2*dot), mask diagonal, accumulate row partials
        const int gj0 = j * 128 + warp_n * 64 + (lane & 3) * 2;
        #pragma unroll
        for (int mi = 0; mi < 2; ++mi) {
            const int gi0 = i0 + warp_m * 32 + mi * 16 + (lane >> 2);
            #pragma unroll
            for (int ni = 0; ni < 8; ++ni) {
                const int gj = gj0 + ni * 8;
                float e00 = __expf(acc[mi][ni][0] * 2.f);
                float e01 = __expf(acc[mi][ni][1] * 2.f);
                float e10 = __expf(acc[mi][ni][2] * 2.f);
                float e11 = __expf(acc[mi][ni][3] * 2.f);
                if (gi0 == gj)         e00 = 0.f;
                if (gi0 == gj + 1)     e01 = 0.f;
                if (gi0 + 8 == gj)     e10 = 0.f;
                if (gi0 + 8 == gj + 1) e11 = 0.f;
                racc[mi * 2 + 0] += e00 + e01;
                racc[mi * 2 + 1] += e10 + e11;
            }
        }
        __syncthreads();                       // all reads of sB[j&1] done
    }

    // reduce across the 4 lanes of each quad (same row, different cols)
    #pragma unroll
    for (int s = 0; s < 4; ++s) {
        racc[s] += __shfl_xor_sync(0xFFFFFFFFu, racc[s], 1);
        racc[s] += __shfl_xor_sync(0xFFFFFFFFu, racc[s], 2);
    }
    if ((lane & 3) == 0) {
        #pragma unroll
        for (int s = 0; s < 4; ++s) {
            int row = warp_m * 32 + (s >> 1) * 16 + (s & 1) * 8 + (lane >> 2);
            atomicAdd(&s_rowsum[row], racc[s]);   // exactly 2 adds/row: deterministic
        }
    }
    __syncthreads();

    if (tid < 128) {
        float lg = logf(s_rowsum[tid]);
        #pragma unroll
        for (int o = 16; o > 0; o >>= 1) lg += __shfl_xor_sync(0xFFFFFFFFu, lg, o);
        if (lane == 0) s_red[tid >> 5] = lg;
    }
    __syncthreads();
    if (tid == 0)
        g_neg_partials[blockIdx.x] = s_red[0] + s_red[1] + s_red[2] + s_red[3];
}

// ---------------------------------------------------------------------------
// Kernel 3: final deterministic reduction -> scalar loss
// ---------------------------------------------------------------------------
__global__ __launch_bounds__(256) void k_final(float* __restrict__ out) {
    __shared__ float rp[256], rn[256];
    int tid = threadIdx.x;
    float sp = 0.f, sn = 0.f;
    for (int i = tid; i < 4096; i += 256)   sp += g_pos_partials[i];
    for (int i = tid; i < NB * 4; i += 256) sn += g_neg_partials[i];
    rp[tid] = sp; rn[tid] = sn;
    __syncthreads();
    for (int o = 128; o > 0; o >>= 1) {
        if (tid < o) { rp[tid] += rp[tid + o]; rn[tid] += rn[tid + o]; }
        __syncthreads();
    }
    if (tid == 0) {
        float loss_neg = rn[0] / (float)(NB * MSZ);
        float loss_pos = rp[0] * 2.0f / (float)NROWS;
        out[0] = loss_neg - loss_pos;
    }
}

// ---------------------------------------------------------------------------
extern "C" void kernel_launch(void* const* d_in, const int* in_sizes, int n_in,
                              void* d_out, int out_size) {
    const float* x  = (const float*)d_in[0];
    const float* xp = (const float*)d_in[1];
    float* out = (float*)d_out;

    cudaFuncSetAttribute(k_neg, cudaFuncAttributeMaxDynamicSharedMemorySize, SMEM_DYN);

    k_prep<<<NROWS / 8, 256>>>(x, xp);
    k_neg<<<NB * 4, 256, SMEM_DYN>>>();
    k_final<<<1, 256>>>(out);
}